// round 1
// baseline (speedup 1.0000x reference)
#include <cuda_runtime.h>

#define BB 32
#define NN 256
#define DD 128
#define NEG_MASK (-9000000.0f)
#define LEAK 0.2f

// Scratch for masked relation scores (allowed: __device__ globals)
__device__ float g_s1[BB * NN * NN];
__device__ float g_s2[BB * NN * NN];

// ---------------------------------------------------------------------------
// Kernel A: masked gated relation scores for both embeddings.
// grid (N/16, B), 256 threads. smem: hiw[2][16][4][132] + hj[2][128][132]
// ---------------------------------------------------------------------------
#define TI 16
#define PITCH 132           // floats per row (conflict-free for float4 phases)
#define P4 33               // float4 per row
#define HIW_ROWS (2 * TI * 4)    // 128 rows
#define HJ_ROWS (2 * 128)        // 256 rows
#define SMEM_FLOATS ((HIW_ROWS + HJ_ROWS) * PITCH)  // 50688 floats = 202752 B

extern __shared__ float sm[];

__global__ __launch_bounds__(256, 1) void scores_kernel(
    const float* __restrict__ sem, const float* __restrict__ strv,
    const int* __restrict__ adj,
    const float* __restrict__ aw, const float* __restrict__ swt)
{
    const int b = blockIdx.y;
    const int i0 = blockIdx.x * TI;
    const int tid = threadIdx.x;

    float* sm_hiw = sm;
    float* sm_hj = sm + HIW_ROWS * PITCH;

    // Load hiw[e][i][r][d] = h_e[b][i0+i][d] * w_e[r][d]   (16384 elements)
    for (int idx = tid; idx < 2 * TI * 4 * DD; idx += 256) {
        int d = idx & 127;
        int r = (idx >> 7) & 3;
        int i = (idx >> 9) & (TI - 1);
        int e = idx >> 13;
        const float* h = e ? strv : sem;
        const float* w = e ? swt : aw;
        sm_hiw[((e * TI + i) * 4 + r) * PITCH + d] =
            h[((b * NN) + i0 + i) * DD + d] * w[r * DD + d];
    }

    const int w8 = tid >> 5, lane = tid & 31;
    const int jgrp = w8 & 3, ihalf = w8 >> 2;
    const int ibase = ihalf * 8;

    for (int c = 0; c < 2; c++) {
        const int j0 = c * 128;
        __syncthreads();
        // Stage hj chunk [2][128][128] (8192 float4, 32 per thread, coalesced)
        for (int idx = tid; idx < 2 * 128 * (DD / 4); idx += 256) {
            int d4 = idx & 31;
            int jl = (idx >> 5) & 127;
            int e = idx >> 12;
            const float* h = e ? strv : sem;
            float4 v = ((const float4*)(h + ((b * NN) + j0 + jl) * DD))[d4];
            ((float4*)sm_hj)[(e * 128 + jl) * P4 + d4] = v;
        }
        __syncthreads();

        const int j = j0 + jgrp * 32 + lane;

        int offS[8], offT[8], msk[8];
#pragma unroll
        for (int ii = 0; ii < 8; ii++) {
            int a = adj[((b * NN) + i0 + ibase + ii) * NN + j];
            msk[ii] = a;
            int r = a > 0 ? a - 1 : 0;
            offS[ii] = ((0 * TI + ibase + ii) * 4 + r) * P4;
            offT[ii] = ((1 * TI + ibase + ii) * 4 + r) * P4;
        }

        float as[8], at[8];
#pragma unroll
        for (int ii = 0; ii < 8; ii++) { as[ii] = 0.f; at[ii] = 0.f; }

        const float4* hiw4 = (const float4*)sm_hiw;
        const float4* hjS = (const float4*)sm_hj + (0 * 128 + jgrp * 32 + lane) * P4;
        const float4* hjT = (const float4*)sm_hj + (1 * 128 + jgrp * 32 + lane) * P4;

#pragma unroll 4
        for (int d4 = 0; d4 < 32; d4++) {
            float4 hs = hjS[d4];
            float4 ht = hjT[d4];
#pragma unroll
            for (int ii = 0; ii < 8; ii++) {
                float4 ws = hiw4[offS[ii] + d4];
                float4 wt = hiw4[offT[ii] + d4];
                as[ii] += ws.x * hs.x + ws.y * hs.y + ws.z * hs.z + ws.w * hs.w;
                at[ii] += wt.x * ht.x + wt.y * ht.y + wt.z * ht.z + wt.w * ht.w;
            }
        }

#pragma unroll
        for (int ii = 0; ii < 8; ii++) {
            int gi = i0 + ibase + ii;
            float v1, v2;
            if (msk[ii] > 0) {
                v1 = as[ii] >= 0.f ? as[ii] : LEAK * as[ii];
                v2 = at[ii] >= 0.f ? at[ii] : LEAK * at[ii];
            } else {
                v1 = NEG_MASK;
                v2 = NEG_MASK;
            }
            g_s1[((b * NN) + gi) * NN + j] = v1;
            g_s2[((b * NN) + gi) * NN + j] = v2;
        }
    }
}

// ---------------------------------------------------------------------------
// Kernel B: per-row entmax-bisect (warp per row), combine, renorm, output GEMV
// grid (N/8, B), 256 threads
// ---------------------------------------------------------------------------
__device__ __forceinline__ float warpsum(float v) {
#pragma unroll
    for (int o = 16; o; o >>= 1) v += __shfl_xor_sync(0xffffffffu, v, o);
    return v;
}
__device__ __forceinline__ float warpmax(float v) {
#pragma unroll
    for (int o = 16; o; o >>= 1) v = fmaxf(v, __shfl_xor_sync(0xffffffffu, v, o));
    return v;
}

template <int MODE>
__device__ __forceinline__ float pfun(float z, float inv) {
    float t = fmaxf(z, 0.f);
    if (MODE == 2) return t * t;     // alpha = 1.5
    if (MODE == 1) return t;         // alpha = 2.0 (sparsemax)
    return __powf(t, inv);           // generic fallback
}

template <int MODE>
__device__ void entmax_warp(const float* __restrict__ srow, float am1, float inv,
                            float* wout, int lane)
{
    float Xs[8];
    float mx = -3.4e38f;
#pragma unroll
    for (int k = 0; k < 8; k++) {
        Xs[k] = srow[lane + 32 * k] * am1;
        mx = fmaxf(mx, Xs[k]);
    }
    mx = warpmax(mx);

    float tau = mx - 1.f;                    // tau_lo
    float dm = 1.f - exp2f(-8.f * am1);      // tau_hi - tau_lo, (1/256)^am1 = 2^(-8 am1)

    float s = 0.f;
#pragma unroll
    for (int k = 0; k < 8; k++) s += pfun<MODE>(Xs[k] - tau, inv);
    float flo = warpsum(s) - 1.f;

#pragma unroll 1
    for (int it = 0; it < 30; it++) {
        dm *= 0.5f;
        float tm = tau + dm;
        float ss = 0.f;
#pragma unroll
        for (int k = 0; k < 8; k++) ss += pfun<MODE>(Xs[k] - tm, inv);
        ss = warpsum(ss);
        float fm = ss - 1.f;
        if (fm * flo >= 0.f) tau = tm;
    }

    float S = 0.f;
    float p[8];
#pragma unroll
    for (int k = 0; k < 8; k++) {
        p[k] = pfun<MODE>(Xs[k] - tau, inv);
        S += p[k];
    }
    S = warpsum(S);
    float r = 1.f / S;
#pragma unroll
    for (int k = 0; k < 8; k++) wout[k] = p[k] * r;
}

__device__ __forceinline__ void entmax_dispatch(const float* srow, float alpha,
                                                float* wout, int lane)
{
    float am1 = alpha - 1.f;
    float inv = 1.f / am1;
    if (fabsf(inv - 2.f) < 1e-5f)      entmax_warp<2>(srow, am1, inv, wout, lane);
    else if (fabsf(inv - 1.f) < 1e-5f) entmax_warp<1>(srow, am1, inv, wout, lane);
    else                               entmax_warp<0>(srow, am1, inv, wout, lane);
}

__global__ __launch_bounds__(256, 1) void combine_kernel(
    const float* __restrict__ sem,
    const float* __restrict__ alpha1p, const float* __restrict__ alpha2p,
    float* __restrict__ out)
{
    __shared__ float wsm[8][NN];
    const int b = blockIdx.y;
    const int i0 = blockIdx.x * 8;
    const int tid = threadIdx.x;
    const int w = tid >> 5, lane = tid & 31;
    const int row = i0 + w;

    const float* s1row = g_s1 + ((b * NN) + row) * NN;
    const float* s2row = g_s2 + ((b * NN) + row) * NN;

    float w1[8], w2[8];
    entmax_dispatch(s1row, alpha1p[0], w1, lane);
    entmax_dispatch(s2row, alpha2p[0], w2, lane);

    float wf[8];
    float s = 0.f;
#pragma unroll
    for (int k = 0; k < 8; k++) { wf[k] = w1[k] * w2[k]; s += wf[k]; }
    s = warpsum(s) + 1e-7f;
    float rinv = 1.f / s;
#pragma unroll
    for (int k = 0; k < 8; k++) wsm[w][lane + 32 * k] = wf[k] * rinv;

    __syncthreads();

    // Output GEMV: thread t -> d4 = t&31, row-group = t>>5 (one of 8 rows)
    const int d4 = tid & 31, rg = tid >> 5;
    float4 acc = make_float4(0.f, 0.f, 0.f, 0.f);
    const float4* semb = (const float4*)(sem + b * NN * DD);
#pragma unroll 4
    for (int j = 0; j < NN; j++) {
        float4 v = semb[j * 32 + d4];
        float swt = wsm[rg][j];
        acc.x += swt * v.x;
        acc.y += swt * v.y;
        acc.z += swt * v.z;
        acc.w += swt * v.w;
    }
    ((float4*)(out + ((b * NN) + i0 + rg) * DD))[d4] = acc;
}

// ---------------------------------------------------------------------------
extern "C" void kernel_launch(void* const* d_in, const int* in_sizes, int n_in,
                              void* d_out, int out_size)
{
    const float* sem  = (const float*)d_in[0];
    const float* strv = (const float*)d_in[1];
    const int*   adj  = (const int*)d_in[2];
    const float* aw   = (const float*)d_in[3];
    const float* swt  = (const float*)d_in[4];
    const float* a1   = (const float*)d_in[5];
    const float* a2   = (const float*)d_in[6];
    float* out = (float*)d_out;

    cudaFuncSetAttribute(scores_kernel,
                         cudaFuncAttributeMaxDynamicSharedMemorySize,
                         SMEM_FLOATS * (int)sizeof(float));

    scores_kernel<<<dim3(NN / TI, BB), 256, SMEM_FLOATS * sizeof(float)>>>(
        sem, strv, adj, aw, swt);
    combine_kernel<<<dim3(NN / 8, BB), 256>>>(sem, a1, a2, out);
}

// round 3
// speedup vs baseline: 1.1867x; 1.1867x over previous
#include <cuda_runtime.h>

#define BB 32
#define NN 256
#define DD 128
#define NEG_MASK (-9000000.0f)
#define LEAK 0.2f

// Scratch for masked relation scores (allowed: __device__ globals)
__device__ float g_s1[BB * NN * NN];
__device__ float g_s2[BB * NN * NN];

// ---------------------------------------------------------------------------
// f32x2 packed-math helpers (Blackwell FFMA2 — only reachable via PTX)
// ---------------------------------------------------------------------------
typedef unsigned long long ull;

__device__ __forceinline__ ull fma2(ull a, ull b, ull c) {
    ull d;
    asm("fma.rn.f32x2 %0, %1, %2, %3;" : "=l"(d) : "l"(a), "l"(b), "l"(c));
    return d;
}
__device__ __forceinline__ ull pack2(float lo, float hi) {
    ull d;
    asm("mov.b64 %0, {%1, %2};" : "=l"(d) : "f"(lo), "f"(hi));
    return d;
}
__device__ __forceinline__ void unpack2(ull v, float& lo, float& hi) {
    asm("mov.b64 {%0, %1}, %2;" : "=f"(lo), "=f"(hi) : "l"(v));
}

// ---------------------------------------------------------------------------
// Kernel A: masked gated relation scores for both embeddings.
// grid (N/16, B), 256 threads.
// smem: hiw[2][16][32 d4][4 r] float4 (r-contiguous for broadcast dedup)
//       + hj[2][128][132]
// ---------------------------------------------------------------------------
#define TI 16
#define PITCH 132
#define P4 33
#define HIW_FLOATS (2 * TI * 4 * DD)          // 16384 floats (65536 B)
#define HJ_FLOATS (2 * 128 * PITCH)           // 33792 floats (135168 B)
#define SMEM_FLOATS (HIW_FLOATS + HJ_FLOATS)  // 200704 B

extern __shared__ float sm[];

__global__ __launch_bounds__(256, 1) void scores_kernel(
    const float* __restrict__ sem, const float* __restrict__ strv,
    const int* __restrict__ adj,
    const float* __restrict__ aw, const float* __restrict__ swt)
{
    const int b = blockIdx.y;
    const int i0 = blockIdx.x * TI;
    const int tid = threadIdx.x;

    float* sm_hiw = sm;
    float* sm_hj = sm + HIW_FLOATS;

    // Build hiw: float4 index = (e*16+i)*128 + d4*4 + r ; component = d&3
    for (int idx = tid; idx < 2 * TI * 4 * DD; idx += 256) {
        int d = idx & 127;
        int r = (idx >> 7) & 3;
        int i = (idx >> 9) & (TI - 1);
        int e = idx >> 13;
        const float* h = e ? strv : sem;
        const float* w = e ? swt : aw;
        int f4 = ((e * TI + i) * 128) + ((d >> 2) << 2) + r;
        sm_hiw[f4 * 4 + (d & 3)] =
            h[((b * NN) + i0 + i) * DD + d] * w[r * DD + d];
    }

    const int w8 = tid >> 5, lane = tid & 31;
    const int jgrp = w8 & 3, ihalf = w8 >> 2;
    const int ibase = ihalf * 8;

    for (int c = 0; c < 2; c++) {
        const int j0 = c * 128;
        __syncthreads();
        // Stage hj chunk [2][128][128] into pitched smem
        for (int idx = tid; idx < 2 * 128 * (DD / 4); idx += 256) {
            int d4 = idx & 31;
            int jl = (idx >> 5) & 127;
            int e = idx >> 12;
            const float* h = e ? strv : sem;
            float4 v = ((const float4*)(h + ((b * NN) + j0 + jl) * DD))[d4];
            ((float4*)sm_hj)[(e * 128 + jl) * P4 + d4] = v;
        }
        __syncthreads();

        const int j = j0 + jgrp * 32 + lane;

        int offS[8], offT[8], msk[8];
#pragma unroll
        for (int ii = 0; ii < 8; ii++) {
            int a = adj[((b * NN) + i0 + ibase + ii) * NN + j];
            msk[ii] = a;
            int r = a > 0 ? a - 1 : 0;
            offS[ii] = (0 * TI + ibase + ii) * 128 + r;   // float4 units
            offT[ii] = (1 * TI + ibase + ii) * 128 + r;
        }

        ull accS[8], accT[8];
#pragma unroll
        for (int ii = 0; ii < 8; ii++) { accS[ii] = 0ull; accT[ii] = 0ull; }

        const ulonglong2* hiw2 = (const ulonglong2*)sm_hiw;
        const ulonglong2* hjS =
            (const ulonglong2*)sm_hj + (0 * 128 + jgrp * 32 + lane) * P4;
        const ulonglong2* hjT =
            (const ulonglong2*)sm_hj + (1 * 128 + jgrp * 32 + lane) * P4;

#pragma unroll 4
        for (int d4 = 0; d4 < 32; d4++) {
            ulonglong2 hs = hjS[d4];
            ulonglong2 ht = hjT[d4];
            int dbase = d4 << 2;
#pragma unroll
            for (int ii = 0; ii < 8; ii++) {
                ulonglong2 ws = hiw2[offS[ii] + dbase];
                accS[ii] = fma2(ws.x, hs.x, accS[ii]);
                accS[ii] = fma2(ws.y, hs.y, accS[ii]);
                ulonglong2 wt = hiw2[offT[ii] + dbase];
                accT[ii] = fma2(wt.x, ht.x, accT[ii]);
                accT[ii] = fma2(wt.y, ht.y, accT[ii]);
            }
        }

#pragma unroll
        for (int ii = 0; ii < 8; ii++) {
            int gi = i0 + ibase + ii;
            float v1, v2;
            if (msk[ii] > 0) {
                float lo, hi;
                unpack2(accS[ii], lo, hi);
                float as = lo + hi;
                unpack2(accT[ii], lo, hi);
                float at = lo + hi;
                v1 = as >= 0.f ? as : LEAK * as;
                v2 = at >= 0.f ? at : LEAK * at;
            } else {
                v1 = NEG_MASK;
                v2 = NEG_MASK;
            }
            g_s1[((b * NN) + gi) * NN + j] = v1;
            g_s2[((b * NN) + gi) * NN + j] = v2;
        }
    }
}

// ---------------------------------------------------------------------------
// Kernel B: entmax-bisect with 8-lane-group reductions (4 rows/warp, both
// embeds interleaved), then combine + output GEMV (f32x2).
// grid (N/32, B), 256 threads.
// ---------------------------------------------------------------------------
__device__ __forceinline__ float gsum8(float v) {
#pragma unroll
    for (int o = 1; o < 8; o <<= 1) v += __shfl_xor_sync(0xffffffffu, v, o);
    return v;
}
__device__ __forceinline__ float gmax8(float v) {
#pragma unroll
    for (int o = 1; o < 8; o <<= 1) v = fmaxf(v, __shfl_xor_sync(0xffffffffu, v, o));
    return v;
}

template <int MODE>
__device__ __forceinline__ float pf(float z, float inv) {
    float t = fmaxf(z, 0.f);
    if (MODE == 2) return t * t;     // alpha = 1.5
    if (MODE == 1) return t;         // alpha = 2.0 (sparsemax)
    return __powf(t, inv);           // generic
}

template <int MODE>
__device__ __forceinline__ float psum32(const float4* X, float tau, float inv) {
    float4 a = make_float4(0.f, 0.f, 0.f, 0.f);
#pragma unroll
    for (int t = 0; t < 8; t++) {
        a.x += pf<MODE>(X[t].x - tau, inv);
        a.y += pf<MODE>(X[t].y - tau, inv);
        a.z += pf<MODE>(X[t].z - tau, inv);
        a.w += pf<MODE>(X[t].w - tau, inv);
    }
    return (a.x + a.y) + (a.z + a.w);
}

template <int M1, int M2>
__device__ __forceinline__ void entmax_pair(
    const float* __restrict__ s1row, const float* __restrict__ s2row,
    float am1_1, float am1_2, float inv1, float inv2,
    float4* __restrict__ wrow4, float* __restrict__ wscale_slot, int s)
{
    float4 X1[8], X2[8];
    float mx1 = -3.4e38f, mx2 = -3.4e38f;
#pragma unroll
    for (int t = 0; t < 8; t++) {
        float4 v = ((const float4*)s1row)[s + 8 * t];
        v.x *= am1_1; v.y *= am1_1; v.z *= am1_1; v.w *= am1_1;
        X1[t] = v;
        mx1 = fmaxf(mx1, fmaxf(fmaxf(v.x, v.y), fmaxf(v.z, v.w)));
        float4 u = ((const float4*)s2row)[s + 8 * t];
        u.x *= am1_2; u.y *= am1_2; u.z *= am1_2; u.w *= am1_2;
        X2[t] = u;
        mx2 = fmaxf(mx2, fmaxf(fmaxf(u.x, u.y), fmaxf(u.z, u.w)));
    }
    mx1 = gmax8(mx1);
    mx2 = gmax8(mx2);

    float tau1 = mx1 - 1.f, tau2 = mx2 - 1.f;
    float dm1 = 1.f - exp2f(-8.f * am1_1);
    float dm2 = 1.f - exp2f(-8.f * am1_2);

    float flo1 = gsum8(psum32<M1>(X1, tau1, inv1)) - 1.f;
    float flo2 = gsum8(psum32<M2>(X2, tau2, inv2)) - 1.f;

#pragma unroll 1
    for (int it = 0; it < 30; it++) {
        dm1 *= 0.5f;
        dm2 *= 0.5f;
        float tm1 = tau1 + dm1;
        float tm2 = tau2 + dm2;
        float ss1 = psum32<M1>(X1, tm1, inv1);
        float ss2 = psum32<M2>(X2, tm2, inv2);
        ss1 = gsum8(ss1);
        ss2 = gsum8(ss2);
        float fm1 = ss1 - 1.f;
        float fm2 = ss2 - 1.f;
        if (fm1 * flo1 >= 0.f) tau1 = tm1;
        if (fm2 * flo2 >= 0.f) tau2 = tm2;
    }

    // Final: p1, p2, raw product -> smem; partial sums for scale
    float s1 = 0.f, s2 = 0.f, s3 = 0.f;
#pragma unroll
    for (int t = 0; t < 8; t++) {
        float4 p1, p2, wf;
        p1.x = pf<M1>(X1[t].x - tau1, inv1); p2.x = pf<M2>(X2[t].x - tau2, inv2);
        p1.y = pf<M1>(X1[t].y - tau1, inv1); p2.y = pf<M2>(X2[t].y - tau2, inv2);
        p1.z = pf<M1>(X1[t].z - tau1, inv1); p2.z = pf<M2>(X2[t].z - tau2, inv2);
        p1.w = pf<M1>(X1[t].w - tau1, inv1); p2.w = pf<M2>(X2[t].w - tau2, inv2);
        wf.x = p1.x * p2.x; wf.y = p1.y * p2.y;
        wf.z = p1.z * p2.z; wf.w = p1.w * p2.w;
        s1 += (p1.x + p1.y) + (p1.z + p1.w);
        s2 += (p2.x + p2.y) + (p2.z + p2.w);
        s3 += (wf.x + wf.y) + (wf.z + wf.w);
        wrow4[s + 8 * t] = wf;
    }
    s1 = gsum8(s1);
    s2 = gsum8(s2);
    s3 = gsum8(s3);
    // weight = (p1 p2 / (S1 S2)) / (s3/(S1 S2) + 1e-7) = p1 p2 / (s3 + 1e-7 S1 S2)
    float scale = 1.f / (s3 + 1e-7f * s1 * s2);
    if (s == 0) *wscale_slot = scale;
}

__global__ __launch_bounds__(256, 2) void combine_kernel(
    const float* __restrict__ sem,
    const float* __restrict__ alpha1p, const float* __restrict__ alpha2p,
    float* __restrict__ out)
{
    __shared__ float4 wsm4[32][NN / 4];   // 32 rows x 256 weights (raw)
    __shared__ float wscale[32];

    const int b = blockIdx.y;
    const int i0 = blockIdx.x * 32;
    const int tid = threadIdx.x;
    const int w = tid >> 5, lane = tid & 31;
    const int g = lane >> 3, s = lane & 7;
    const int rowLocal = w * 4 + g;
    const int row = i0 + rowLocal;

    const float* s1row = g_s1 + ((b * NN) + row) * NN;
    const float* s2row = g_s2 + ((b * NN) + row) * NN;

    float a1 = alpha1p[0], a2 = alpha2p[0];
    float am1_1 = a1 - 1.f, am1_2 = a2 - 1.f;
    float inv1 = 1.f / am1_1, inv2 = 1.f / am1_2;

    int m1 = (fabsf(a1 - 1.5f) < 1e-4f) ? 2 : ((fabsf(a1 - 2.f) < 1e-4f) ? 1 : 0);
    int m2 = (fabsf(a2 - 1.5f) < 1e-4f) ? 2 : ((fabsf(a2 - 2.f) < 1e-4f) ? 1 : 0);

    if (m1 == 2 && m2 == 1)
        entmax_pair<2, 1>(s1row, s2row, am1_1, am1_2, inv1, inv2,
                          wsm4[rowLocal], &wscale[rowLocal], s);
    else if (m1 == 1 && m2 == 2)
        entmax_pair<1, 2>(s1row, s2row, am1_1, am1_2, inv1, inv2,
                          wsm4[rowLocal], &wscale[rowLocal], s);
    else
        entmax_pair<0, 0>(s1row, s2row, am1_1, am1_2, inv1, inv2,
                          wsm4[rowLocal], &wscale[rowLocal], s);

    __syncthreads();

    // Output GEMV: thread -> d4 = tid&31, 4 rows = (tid>>5)*4 + k  (f32x2 math)
    const int d4 = tid & 31, rbase = (tid >> 5) * 4;
    ull accA[4], accB[4];
#pragma unroll
    for (int k = 0; k < 4; k++) { accA[k] = 0ull; accB[k] = 0ull; }

    const ulonglong2* semb2 = (const ulonglong2*)(sem + b * NN * DD);
    const float* wrow0 = (const float*)wsm4[rbase + 0];
    const float* wrow1 = (const float*)wsm4[rbase + 1];
    const float* wrow2 = (const float*)wsm4[rbase + 2];
    const float* wrow3 = (const float*)wsm4[rbase + 3];

#pragma unroll 4
    for (int j = 0; j < NN; j++) {
        ulonglong2 v = semb2[j * 32 + d4];
        ull w0 = pack2(wrow0[j], wrow0[j]);
        ull w1 = pack2(wrow1[j], wrow1[j]);
        ull w2 = pack2(wrow2[j], wrow2[j]);
        ull w3 = pack2(wrow3[j], wrow3[j]);
        accA[0] = fma2(w0, v.x, accA[0]); accB[0] = fma2(w0, v.y, accB[0]);
        accA[1] = fma2(w1, v.x, accA[1]); accB[1] = fma2(w1, v.y, accB[1]);
        accA[2] = fma2(w2, v.x, accA[2]); accB[2] = fma2(w2, v.y, accB[2]);
        accA[3] = fma2(w3, v.x, accA[3]); accB[3] = fma2(w3, v.y, accB[3]);
    }

#pragma unroll
    for (int k = 0; k < 4; k++) {
        float sc = wscale[rbase + k];
        float4 o;
        unpack2(accA[k], o.x, o.y);
        unpack2(accB[k], o.z, o.w);
        o.x *= sc; o.y *= sc; o.z *= sc; o.w *= sc;
        ((float4*)(out + ((b * NN) + i0 + rbase + k) * DD))[d4] = o;
    }
}

// ---------------------------------------------------------------------------
extern "C" void kernel_launch(void* const* d_in, const int* in_sizes, int n_in,
                              void* d_out, int out_size)
{
    const float* sem  = (const float*)d_in[0];
    const float* strv = (const float*)d_in[1];
    const int*   adj  = (const int*)d_in[2];
    const float* aw   = (const float*)d_in[3];
    const float* swt  = (const float*)d_in[4];
    const float* a1   = (const float*)d_in[5];
    const float* a2   = (const float*)d_in[6];
    float* out = (float*)d_out;

    cudaFuncSetAttribute(scores_kernel,
                         cudaFuncAttributeMaxDynamicSharedMemorySize,
                         SMEM_FLOATS * (int)sizeof(float));

    scores_kernel<<<dim3(NN / TI, BB), 256, SMEM_FLOATS * sizeof(float)>>>(
        sem, strv, adj, aw, swt);
    combine_kernel<<<dim3(NN / 32, BB), 256>>>(sem, a1, a2, out);
}

// round 5
// speedup vs baseline: 1.2024x; 1.0133x over previous
#include <cuda_runtime.h>

#define BB 32
#define NN 256
#define DD 128
#define NEG_MASK (-9000000.0f)
#define LEAK 0.2f

// Scratch for masked relation scores (allowed: __device__ globals)
__device__ float g_s1[BB * NN * NN];
__device__ float g_s2[BB * NN * NN];

// ---------------------------------------------------------------------------
// f32x2 packed-math helpers
// ---------------------------------------------------------------------------
typedef unsigned long long ull;

__device__ __forceinline__ ull fma2(ull a, ull b, ull c) {
    ull d;
    asm("fma.rn.f32x2 %0, %1, %2, %3;" : "=l"(d) : "l"(a), "l"(b), "l"(c));
    return d;
}
__device__ __forceinline__ ull pack2(float lo, float hi) {
    ull d;
    asm("mov.b64 %0, {%1, %2};" : "=l"(d) : "f"(lo), "f"(hi));
    return d;
}
__device__ __forceinline__ void unpack2(ull v, float& lo, float& hi) {
    asm("mov.b64 {%0, %1}, %2;" : "=f"(lo), "=f"(hi) : "l"(v));
}

// ---------------------------------------------------------------------------
// Kernel A: masked gated relation scores. TI=8, one embed at a time.
// smem = hiw[8][32 d4][4 r] float4 (16KB) + hj[128][33] float4 (66KB) = 84KB
// -> 2 CTAs/SM. grid (N/8, B) = 1024 blocks. (Math identical to R3-passing.)
// ---------------------------------------------------------------------------
#define TI 8
#define P4 33
#define HIW_F4 (TI * 4 * (DD / 4))          // 1024 float4 (16384 B)
#define HJ_F4 (128 * P4)                    // 4224 float4 (67584 B)
#define SMEM_BYTES ((HIW_F4 + HJ_F4) * 16)  // 83968 B

extern __shared__ float4 sm4[];

__global__ __launch_bounds__(256, 2) void scores_kernel(
    const float* __restrict__ sem, const float* __restrict__ strv,
    const int* __restrict__ adj,
    const float* __restrict__ aw, const float* __restrict__ swt)
{
    const int b = blockIdx.y;
    const int i0 = blockIdx.x * TI;
    const int tid = threadIdx.x;

    float4* sm_hiw4 = sm4;
    float4* sm_hj4 = sm4 + HIW_F4;

    const int w8 = tid >> 5, lane = tid & 31;
    const int jgrp = w8 & 3, ibase = (w8 >> 2) * 4;
    const int jloc = jgrp * 32 + lane;

    for (int e = 0; e < 2; e++) {
        const float* h = e ? strv : sem;
        const float* wmat = e ? swt : aw;
        float* gs = e ? g_s2 : g_s1;

        __syncthreads();
        // Build hiw: float4 idx = i*128 + d4*4 + r, comp = d&3
        for (int idx = tid; idx < TI * 4 * DD; idx += 256) {
            int d = idx & 127;
            int r = (idx >> 7) & 3;
            int i = idx >> 9;
            ((float*)sm_hiw4)[(i * 128 + ((d >> 2) << 2) + r) * 4 + (d & 3)] =
                h[((b * NN) + i0 + i) * DD + d] * wmat[r * DD + d];
        }

        for (int c = 0; c < 2; c++) {
            __syncthreads();
            // Stage hj chunk [128 j][128 d] (coalesced)
            for (int idx = tid; idx < 128 * (DD / 4); idx += 256) {
                int d4 = idx & 31;
                int jl = idx >> 5;
                sm_hj4[jl * P4 + d4] =
                    ((const float4*)(h + ((b * NN) + c * 128 + jl) * DD))[d4];
            }
            __syncthreads();

            const int j = c * 128 + jloc;

            int msk[4], off[4];
#pragma unroll
            for (int ii = 0; ii < 4; ii++) {
                int a = adj[((b * NN) + i0 + ibase + ii) * NN + j];
                msk[ii] = a;
                int r = a > 0 ? a - 1 : 0;
                off[ii] = (ibase + ii) * 128 + r;   // 16B units
            }

            ull acc[4];
#pragma unroll
            for (int ii = 0; ii < 4; ii++) acc[ii] = 0ull;

            const ulonglong2* hiw2 = (const ulonglong2*)sm_hiw4;
            const ulonglong2* hj2 = (const ulonglong2*)sm_hj4 + jloc * P4;

#pragma unroll 8
            for (int d4 = 0; d4 < 32; d4++) {
                ulonglong2 hv = hj2[d4];
                int dbase = d4 << 2;
#pragma unroll
                for (int ii = 0; ii < 4; ii++) {
                    ulonglong2 wv = hiw2[off[ii] + dbase];
                    acc[ii] = fma2(wv.x, hv.x, acc[ii]);
                    acc[ii] = fma2(wv.y, hv.y, acc[ii]);
                }
            }

#pragma unroll
            for (int ii = 0; ii < 4; ii++) {
                float lo, hi;
                unpack2(acc[ii], lo, hi);
                float v = lo + hi;
                v = msk[ii] > 0 ? (v >= 0.f ? v : LEAK * v) : NEG_MASK;
                gs[((b * NN) + i0 + ibase + ii) * NN + j] = v;
            }
        }
    }
}

// ---------------------------------------------------------------------------
// Kernel B: entmax 30-bisect (reference-faithful), 2 rows/warp via 16-lane
// groups, combine + output GEMV (f32x2). grid (N/16, B) = 512 CTAs.
// ---------------------------------------------------------------------------
__device__ __forceinline__ float gsum16(float v) {
#pragma unroll
    for (int o = 1; o < 16; o <<= 1) v += __shfl_xor_sync(0xffffffffu, v, o);
    return v;
}
__device__ __forceinline__ float gmax16(float v) {
#pragma unroll
    for (int o = 1; o < 16; o <<= 1) v = fmaxf(v, __shfl_xor_sync(0xffffffffu, v, o));
    return v;
}

template <int MODE>
__device__ __forceinline__ float pf(float z, float inv) {
    float t = fmaxf(z, 0.f);
    if (MODE == 2) return t * t;     // alpha = 1.5
    if (MODE == 1) return t;         // alpha = 2.0 (sparsemax)
    return __powf(t, inv);           // generic
}

template <int MODE>
__device__ __forceinline__ float psum16(const float4* X, float tau, float inv) {
    float4 a = make_float4(0.f, 0.f, 0.f, 0.f);
#pragma unroll
    for (int t = 0; t < 4; t++) {
        a.x += pf<MODE>(X[t].x - tau, inv);
        a.y += pf<MODE>(X[t].y - tau, inv);
        a.z += pf<MODE>(X[t].z - tau, inv);
        a.w += pf<MODE>(X[t].w - tau, inv);
    }
    return (a.x + a.y) + (a.z + a.w);
}

template <int M1, int M2>
__device__ __forceinline__ void entmax_pair(
    const float* __restrict__ s1row, const float* __restrict__ s2row,
    float am1_1, float am1_2, float inv1, float inv2,
    float4* __restrict__ wrow4, float* __restrict__ wscale_slot, int s)
{
    float4 X1[4], X2[4];
    float mx1 = -3.4e38f, mx2 = -3.4e38f;
#pragma unroll
    for (int t = 0; t < 4; t++) {
        float4 v = ((const float4*)s1row)[s + 16 * t];
        v.x *= am1_1; v.y *= am1_1; v.z *= am1_1; v.w *= am1_1;
        X1[t] = v;
        mx1 = fmaxf(mx1, fmaxf(fmaxf(v.x, v.y), fmaxf(v.z, v.w)));
        float4 u = ((const float4*)s2row)[s + 16 * t];
        u.x *= am1_2; u.y *= am1_2; u.z *= am1_2; u.w *= am1_2;
        X2[t] = u;
        mx2 = fmaxf(mx2, fmaxf(fmaxf(u.x, u.y), fmaxf(u.z, u.w)));
    }
    mx1 = gmax16(mx1);
    mx2 = gmax16(mx2);

    float tau1 = mx1 - 1.f, tau2 = mx2 - 1.f;
    float dm1 = 1.f - exp2f(-8.f * am1_1);
    float dm2 = 1.f - exp2f(-8.f * am1_2);

    float flo1 = gsum16(psum16<M1>(X1, tau1, inv1)) - 1.f;
    float flo2 = gsum16(psum16<M2>(X2, tau2, inv2)) - 1.f;

#pragma unroll 1
    for (int it = 0; it < 30; it++) {
        dm1 *= 0.5f;
        dm2 *= 0.5f;
        float tm1 = tau1 + dm1;
        float tm2 = tau2 + dm2;
        float ss1 = psum16<M1>(X1, tm1, inv1);
        float ss2 = psum16<M2>(X2, tm2, inv2);
        ss1 = gsum16(ss1);
        ss2 = gsum16(ss2);
        if ((ss1 - 1.f) * flo1 >= 0.f) tau1 = tm1;
        if ((ss2 - 1.f) * flo2 >= 0.f) tau2 = tm2;
    }

    // Final: raw product -> smem; partial sums for the combined scale
    float s1 = 0.f, s2 = 0.f, s3 = 0.f;
#pragma unroll
    for (int t = 0; t < 4; t++) {
        float4 p1, p2, wf;
        p1.x = pf<M1>(X1[t].x - tau1, inv1); p2.x = pf<M2>(X2[t].x - tau2, inv2);
        p1.y = pf<M1>(X1[t].y - tau1, inv1); p2.y = pf<M2>(X2[t].y - tau2, inv2);
        p1.z = pf<M1>(X1[t].z - tau1, inv1); p2.z = pf<M2>(X2[t].z - tau2, inv2);
        p1.w = pf<M1>(X1[t].w - tau1, inv1); p2.w = pf<M2>(X2[t].w - tau2, inv2);
        wf.x = p1.x * p2.x; wf.y = p1.y * p2.y;
        wf.z = p1.z * p2.z; wf.w = p1.w * p2.w;
        s1 += (p1.x + p1.y) + (p1.z + p1.w);
        s2 += (p2.x + p2.y) + (p2.z + p2.w);
        s3 += (wf.x + wf.y) + (wf.z + wf.w);
        wrow4[s + 16 * t] = wf;
    }
    s1 = gsum16(s1);
    s2 = gsum16(s2);
    s3 = gsum16(s3);
    // weight = (p1p2/(S1S2)) / (s3/(S1S2) + 1e-7) = p1p2 / (s3 + 1e-7 S1 S2)
    float scale = 1.f / (s3 + 1e-7f * s1 * s2);
    if (s == 0) *wscale_slot = scale;
}

__global__ __launch_bounds__(256, 4) void combine_kernel(
    const float* __restrict__ sem,
    const float* __restrict__ alpha1p, const float* __restrict__ alpha2p,
    float* __restrict__ out)
{
    __shared__ float4 wsm4[16][NN / 4];   // 16 rows x 256 raw weights
    __shared__ float wscale[16];

    const int b = blockIdx.y;
    const int i0 = blockIdx.x * 16;
    const int tid = threadIdx.x;
    const int w = tid >> 5, lane = tid & 31;
    const int g = lane >> 4, s = lane & 15;
    const int rowLocal = w * 2 + g;       // 0..15
    const int row = i0 + rowLocal;

    const float* s1row = g_s1 + ((b * NN) + row) * NN;
    const float* s2row = g_s2 + ((b * NN) + row) * NN;

    float a1 = alpha1p[0], a2 = alpha2p[0];
    float am1_1 = a1 - 1.f, am1_2 = a2 - 1.f;
    float inv1 = 1.f / am1_1, inv2 = 1.f / am1_2;

    int m1 = (fabsf(a1 - 1.5f) < 1e-4f) ? 2 : ((fabsf(a1 - 2.f) < 1e-4f) ? 1 : 0);
    int m2 = (fabsf(a2 - 1.5f) < 1e-4f) ? 2 : ((fabsf(a2 - 2.f) < 1e-4f) ? 1 : 0);

    if (m1 == 2 && m2 == 1)
        entmax_pair<2, 1>(s1row, s2row, am1_1, am1_2, inv1, inv2,
                          wsm4[rowLocal], &wscale[rowLocal], s);
    else if (m1 == 1 && m2 == 2)
        entmax_pair<1, 2>(s1row, s2row, am1_1, am1_2, inv1, inv2,
                          wsm4[rowLocal], &wscale[rowLocal], s);
    else if (m1 == 2 && m2 == 2)
        entmax_pair<2, 2>(s1row, s2row, am1_1, am1_2, inv1, inv2,
                          wsm4[rowLocal], &wscale[rowLocal], s);
    else if (m1 == 1 && m2 == 1)
        entmax_pair<1, 1>(s1row, s2row, am1_1, am1_2, inv1, inv2,
                          wsm4[rowLocal], &wscale[rowLocal], s);
    else
        entmax_pair<0, 0>(s1row, s2row, am1_1, am1_2, inv1, inv2,
                          wsm4[rowLocal], &wscale[rowLocal], s);

    __syncthreads();

    // Output GEMV: thread -> d4 = tid&31, 2 rows = (tid>>5)*2 + k
    const int d4 = tid & 31, rbase = (tid >> 5) * 2;
    ull accA[2], accB[2];
#pragma unroll
    for (int k = 0; k < 2; k++) { accA[k] = 0ull; accB[k] = 0ull; }

    const ulonglong2* semb2 = (const ulonglong2*)(sem + b * NN * DD);
    const float* wrow0 = (const float*)wsm4[rbase + 0];
    const float* wrow1 = (const float*)wsm4[rbase + 1];

#pragma unroll 4
    for (int j = 0; j < NN; j++) {
        ulonglong2 v = semb2[j * 32 + d4];
        ull w0 = pack2(wrow0[j], wrow0[j]);
        ull w1 = pack2(wrow1[j], wrow1[j]);
        accA[0] = fma2(w0, v.x, accA[0]); accB[0] = fma2(w0, v.y, accB[0]);
        accA[1] = fma2(w1, v.x, accA[1]); accB[1] = fma2(w1, v.y, accB[1]);
    }

#pragma unroll
    for (int k = 0; k < 2; k++) {
        float sc = wscale[rbase + k];
        float4 o;
        unpack2(accA[k], o.x, o.y);
        unpack2(accB[k], o.z, o.w);
        o.x *= sc; o.y *= sc; o.z *= sc; o.w *= sc;
        ((float4*)(out + ((b * NN) + i0 + rbase + k) * DD))[d4] = o;
    }
}

// ---------------------------------------------------------------------------
extern "C" void kernel_launch(void* const* d_in, const int* in_sizes, int n_in,
                              void* d_out, int out_size)
{
    const float* sem  = (const float*)d_in[0];
    const float* strv = (const float*)d_in[1];
    const int*   adj  = (const int*)d_in[2];
    const float* aw   = (const float*)d_in[3];
    const float* swt  = (const float*)d_in[4];
    const float* a1   = (const float*)d_in[5];
    const float* a2   = (const float*)d_in[6];
    float* out = (float*)d_out;

    cudaFuncSetAttribute(scores_kernel,
                         cudaFuncAttributeMaxDynamicSharedMemorySize,
                         SMEM_BYTES);

    scores_kernel<<<dim3(NN / TI, BB), 256, SMEM_BYTES>>>(
        sem, strv, adj, aw, swt);
    combine_kernel<<<dim3(NN / 16, BB), 256>>>(sem, a1, a2, out);
}